// round 16
// baseline (speedup 1.0000x reference)
#include <cuda_runtime.h>
#include <math.h>
#include <float.h>

// Pipelined two-phase router:
//  K1 (pool):  patch (N,32,8,8) f32 -> per-channel means into 4MB scratch.
//  K2 (route): scratch -> weights_filtered (N,16). One thread per patch.
// Both are chunked (8 chunks); K2 chunk c runs on a second stream gated by an
// event on K1 chunk c, so routing overlaps the next pooling chunk's DRAM
// streaming. Only the last K2 chunk (~1.5us) is exposed.

#define EXPERTS 16
#define CHANNELS 32
#define MAX_PATCHES 32768
#define PATCH_F4 512            // 32*64 floats / 4
#define NCHUNK 8

__device__ __align__(16) float g_emb[MAX_PATCHES * CHANNELS];   // 4MB scratch

// ---------------------------------------------------------------------------
// Kernel 1: pooling (per chunk). Thread t handles 4 consecutive float4 (64B)
// — one quarter of one channel. shfl_xor{1,2} combine; lanes 0-7 store 32B.
// ---------------------------------------------------------------------------
__global__ __launch_bounds__(256) void pool_kernel(
    const float* __restrict__ patch_chunk,   // already offset to chunk start
    int patch_start, int n_f4)
{
    const int gid  = blockIdx.x * 256 + threadIdx.x;
    const int base = gid * 4;
    if (base >= n_f4) return;

    const float4* p4 = reinterpret_cast<const float4*>(patch_chunk);
    float s = 0.0f;
#pragma unroll
    for (int i = 0; i < 4; i++) {
        float4 t = __ldcs(&p4[base + i]);
        s += (t.x + t.y) + (t.z + t.w);
    }
    s += __shfl_xor_sync(0xFFFFFFFFu, s, 1);
    s += __shfl_xor_sync(0xFFFFFFFFu, s, 2);
    const int lane = threadIdx.x & 31;
    const float v = __shfl_sync(0xFFFFFFFFu, s, (lane & 7) * 4);
    if (lane < 8) {
        const int g_base = ((gid & ~31) >> 2);    // first channel-id of warp (chunk-local)
        g_emb[patch_start * CHANNELS + g_base + lane] = v * (1.0f / 64.0f);
    }
}

// ---------------------------------------------------------------------------
// Kernel 2: routing (per chunk), one thread per patch.
// ---------------------------------------------------------------------------
#define K2_THREADS 128

__global__ __launch_bounds__(K2_THREADS) void route_kernel(
    const float* __restrict__ keys,
    const float* __restrict__ temp_p,
    const float* __restrict__ beta_p,
    const float* __restrict__ thr_p,
    float* __restrict__ out,
    int patch_start, int n_chunk)
{
    __shared__ __align__(16) float keys_s[EXPERTS * 36];   // 16B-aligned rows

    const int tid = threadIdx.x;
    for (int i = tid; i < EXPERTS * CHANNELS; i += K2_THREADS) {
        int e = i >> 5, c = i & 31;
        keys_s[e * 36 + c] = keys[i];
    }

    const float inv_temp = 1.0f / (*temp_p);
    const float beta     = (*beta_p) + 1e-8f;
    const float thr      = *thr_p;
    __syncthreads();

    const int local = blockIdx.x * K2_THREADS + tid;
    if (local >= n_chunk) return;
    const int pid = patch_start + local;

    // ---- Load embedding (8 x LDG.128; written by K1 -> L2-resident).
    float e[CHANNELS];
    const float4* ep = reinterpret_cast<const float4*>(&g_emb[(size_t)pid * CHANNELS]);
#pragma unroll
    for (int i = 0; i < 8; i++) {
        float4 t = ep[i];
        e[4 * i + 0] = t.x; e[4 * i + 1] = t.y;
        e[4 * i + 2] = t.z; e[4 * i + 3] = t.w;
    }

    // ---- Norm ----
    float sq = 0.0f;
#pragma unroll
    for (int c = 0; c < CHANNELS; c++) sq = fmaf(e[c], e[c], sq);
    const float scale = __fdividef(1.0f, fmaxf(sqrtf(sq), 1e-12f)) * inv_temp;

    // ---- Scaled logits (16 dots; keys broadcast from smem as float4) ----
    float x[EXPERTS];
#pragma unroll
    for (int ex = 0; ex < EXPERTS; ex++) {
        const float4* kr = reinterpret_cast<const float4*>(&keys_s[ex * 36]);
        float acc = 0.0f;
#pragma unroll
        for (int i = 0; i < 8; i++) {
            float4 k4 = kr[i];
            acc = fmaf(e[4 * i + 0], k4.x, acc);
            acc = fmaf(e[4 * i + 1], k4.y, acc);
            acc = fmaf(e[4 * i + 2], k4.z, acc);
            acc = fmaf(e[4 * i + 3], k4.w, acc);
        }
        x[ex] = acc * scale + 1e-8f;
    }

    // ---- Softmax; keep x centered for the entropy identity ----
    float mx = x[0];
#pragma unroll
    for (int ex = 1; ex < EXPERTS; ex++) mx = fmaxf(mx, x[ex]);
    float w[EXPERTS];
    float denom = 0.0f;
#pragma unroll
    for (int ex = 0; ex < EXPERTS; ex++) {
        x[ex] -= mx;
        w[ex] = __expf(x[ex]);
        denom += w[ex];
    }
    const float inv_d = __fdividef(1.0f, denom);
#pragma unroll
    for (int ex = 0; ex < EXPERTS; ex++) w[ex] *= inv_d;

    // ---- Moments; entropy via  ln w_i = x_i - ln(denom)  (no per-expert log;
    //      the reference's +1e-18 inside log is negligible: min w ~ 0.04) ----
    float sw = 0.0f, swsq = 0.0f, swx = 0.0f;
#pragma unroll
    for (int ex = 0; ex < EXPERTS; ex++) {
        sw   += w[ex];
        swsq  = fmaf(w[ex], w[ex], swsq);
        swx   = fmaf(w[ex], x[ex], swx);
    }
    const float entropy = __logf(denom) * sw - swx;   // -(sum w (x - lnD))

    // ---- Branchless top-5 (only s0..s4 consumed) ----
    float s0 = -FLT_MAX, s1 = -FLT_MAX, s2 = -FLT_MAX, s3 = -FLT_MAX, s4 = -FLT_MAX;
#pragma unroll
    for (int ex = 0; ex < EXPERTS; ex++) {
        float v = w[ex], b;
        b = fmaxf(s0, v); v = fminf(s0, v); s0 = b;
        b = fmaxf(s1, v); v = fminf(s1, v); s1 = b;
        b = fmaxf(s2, v); v = fminf(s2, v); s2 = b;
        b = fmaxf(s3, v); v = fminf(s3, v); s3 = b;
        s4 = fmaxf(s4, v);
    }

    // ---- Adaptive threshold ----
    const float mean    = sw * (1.0f / 16.0f);
    const float var     = fmaxf(0.0f, (swsq - sw * sw * (1.0f / 16.0f)) * (1.0f / 15.0f));
    const float stdw    = sqrtf(var);

    const float max_comp = 1.0f - s0;
    const float ent_comp = 1.0f - entropy * 0.360673760222f;  // 1/ln(16)
    const float mean_rest = (s1 + s2 + s3 + s4) * 0.25f;
    float gap = __fdividef(s0 - mean_rest, s0 + 1e-8f);
    gap = fminf(fmaxf(gap, 0.0f), 1.0f);

    float adaptive = thr * (0.5f + 0.4f * max_comp + 0.3f * ent_comp + 0.3f * gap);
    const float min_thr = fmaxf(0.05f, mean - 0.5f * stdw);
    const float max_thr = fminf(0.7f, s0 - 0.1f * stdw);
    adaptive = fminf(fmaxf(adaptive, min_thr), max_thr);
    adaptive = fminf(adaptive, s3 * 0.9f);          // kth = sorted[3]

    // ---- Soft mask, filter, renormalize ----
    float swf = 0.0f;
#pragma unroll
    for (int ex = 0; ex < EXPERTS; ex++) {
        const float mask = __fdividef(1.0f, 1.0f + __expf(-beta * (w[ex] - adaptive)));
        w[ex] *= mask;
        swf += w[ex];
    }
    const float inv_s = __fdividef(1.0f, fmaxf(swf, 1e-8f));

    float4* o4 = reinterpret_cast<float4*>(&out[(size_t)pid * EXPERTS]);
#pragma unroll
    for (int j = 0; j < 4; j++)
        o4[j] = make_float4(w[4 * j + 0] * inv_s, w[4 * j + 1] * inv_s,
                            w[4 * j + 2] * inv_s, w[4 * j + 3] * inv_s);
}

extern "C" void kernel_launch(void* const* d_in, const int* in_sizes, int n_in,
                              void* d_out, int out_size)
{
    const float* patch  = (const float*)d_in[0];
    const float* keys   = (const float*)d_in[1];
    const float* temp_p = (const float*)d_in[2];
    const float* beta_p = (const float*)d_in[3];
    const float* thr_p  = (const float*)d_in[4];
    float* out = (float*)d_out;

    const int n_patches = in_sizes[0] / (CHANNELS * 64);   // 32768

    // One-time resources (created on the first, pre-capture correctness call;
    // no device memory is allocated). Work per call is identical.
    static cudaStream_t s2 = nullptr;
    static cudaEvent_t evK1[NCHUNK];
    static cudaEvent_t evJoin = nullptr;
    if (s2 == nullptr) {
        cudaStreamCreateWithFlags(&s2, cudaStreamNonBlocking);
        for (int c = 0; c < NCHUNK; c++)
            cudaEventCreateWithFlags(&evK1[c], cudaEventDisableTiming);
        cudaEventCreateWithFlags(&evJoin, cudaEventDisableTiming);
    }

    const int chunk = (n_patches + NCHUNK - 1) / NCHUNK;

    for (int c = 0; c < NCHUNK; c++) {
        const int p0 = c * chunk;
        if (p0 >= n_patches) break;
        const int np = (n_patches - p0 < chunk) ? (n_patches - p0) : chunk;

        // K1 chunk on the main (capture) stream.
        const int n_f4      = np * PATCH_F4;
        const int k1_blocks = (n_f4 / 4 + 255) / 256;
        pool_kernel<<<k1_blocks, 256, 0, 0>>>(
            patch + (size_t)p0 * (CHANNELS * 64), p0, n_f4);
        cudaEventRecord(evK1[c], 0);

        // K2 chunk on the side stream, gated by its K1 chunk.
        cudaStreamWaitEvent(s2, evK1[c], 0);
        const int k2_blocks = (np + K2_THREADS - 1) / K2_THREADS;
        route_kernel<<<k2_blocks, K2_THREADS, 0, s2>>>(
            keys, temp_p, beta_p, thr_p, out, p0, np);
    }

    // Join the side stream back into the main stream.
    cudaEventRecord(evJoin, s2);
    cudaStreamWaitEvent(0, evJoin, 0);
}